// round 6
// baseline (speedup 1.0000x reference)
#include <cuda_runtime.h>
#include <cuda_fp16.h>
#include <cstdint>

// ============================================================
// FFTEmbedding as implicit-im2col GEMM (sm_100 legacy-HMMA path)
//   out = A(131072x256 Toeplitz windows) @ WeffT(512x256)^T + bias
// R6 (base R4): half-split mainloop w/ inline streaming stores
//   (spread the epilogue store burst), fp16 dual-aligned segment
//   (1 LDS.32 per Toeplitz A-value, preloaded), revert cp.async.
// ============================================================

#define B_SZ   16
#define T_SZ   8192
#define W_SZ   256
#define EMB    512
#define NFEAT  258

#define BM 128
#define BN 128
#define MTILES 1024           // (B*T)/BM
#define GRID   296            // 2 CTAs per SM
#define CTAS_PER_N 74         // GRID / 4 N-tiles
#define THREADS 256

#define PB 264                // B smem pitch in halfs (256 + 8 pad)
#define SMEM_B_BYTES (128 * PB * 2)            // 67584
// seg: [2 buffers][2 alignment variants][384] halfs
#define SMEM_SEG_BYTES (2 * 2 * 384 * 2)       // 3072
#define SMEM_TOTAL   (SMEM_B_BYTES + SMEM_SEG_BYTES)

// fp16 Weff^T, [EMB][W_SZ]
__device__ __half g_weffT[EMB * W_SZ];

__device__ __forceinline__ uint32_t smem_to_u32(const void* p) {
    uint32_t a;
    asm("{ .reg .u64 t; cvta.to.shared.u64 t, %1; cvt.u32.u64 %0, t; }" : "=r"(a) : "l"(p));
    return a;
}

__device__ __forceinline__ uint32_t lds32(uint32_t addr) {
    uint32_t v;
    asm volatile("ld.shared.b32 %0, [%1];" : "=r"(v) : "r"(addr));
    return v;
}

__device__ __forceinline__ void mma16816(float* c, uint32_t a0, uint32_t a1,
                                         uint32_t a2, uint32_t a3,
                                         uint32_t b0, uint32_t b1) {
    asm volatile(
        "mma.sync.aligned.m16n8k16.row.col.f32.f16.f16.f32 "
        "{%0,%1,%2,%3}, {%4,%5,%6,%7}, {%8,%9}, {%0,%1,%2,%3};"
        : "+f"(c[0]), "+f"(c[1]), "+f"(c[2]), "+f"(c[3])
        : "r"(a0), "r"(a1), "r"(a2), "r"(a3), "r"(b0), "r"(b1));
}

__device__ __forceinline__ void ldmatrix_x4(uint32_t& r0, uint32_t& r1,
                                            uint32_t& r2, uint32_t& r3, uint32_t addr) {
    asm volatile("ldmatrix.sync.aligned.m8n8.x4.shared.b16 {%0,%1,%2,%3}, [%4];"
                 : "=r"(r0), "=r"(r1), "=r"(r2), "=r"(r3) : "r"(addr));
}

__device__ __forceinline__ void stcs128(float* p, float4 v) {
    asm volatile("st.global.cs.v4.f32 [%0], {%1,%2,%3,%4};"
                 :: "l"(p), "f"(v.x), "f"(v.y), "f"(v.z), "f"(v.w) : "memory");
}

// Column permutation within each warp's 16-col slice (enables STG.128).
__device__ __host__ __forceinline__ int permcol(int s) {
    return (s < 8) ? ((s & 1) ? 2 * s - 1 : 2 * s)
                   : ((s & 1) ? 2 * s - 15 : 2 * s - 14);
}

// ============================================================
// Kernel 1: Weff^T precompute (angle recurrence)
// ============================================================
__global__ void weff_kernel(const float* __restrict__ weight) {
    __shared__ float w1[129], w2[129];
    const int e = blockIdx.x;
    for (int f = threadIdx.x; f < NFEAT; f += 256) {
        float v = weight[e * NFEAT + f];
        if (f < 129) w1[f] = v; else w2[f - 129] = v;
    }
    __syncthreads();
    const int n = threadIdx.x;                // k position 0..255
    float s1, c1;
    sincospif((float)n / 128.0f, &s1, &c1);   // step angle 2*pi*n/256
    float acc = w1[0];
    float c = c1, s = s1;
    #pragma unroll 4
    for (int kk = 1; kk <= 128; kk++) {
        acc = fmaf(c, w1[kk], acc);
        acc = fmaf(-s, w2[kk], acc);
        float cn = fmaf(c, c1, -s * s1);
        float sn = fmaf(s, c1,  c * s1);
        c = cn; s = sn;
    }
    g_weffT[e * W_SZ + n] = __float2half_rn(acc);
}

// ============================================================
// Kernel 2: persistent GEMM, grid=296 (2 CTAs/SM), 256 threads
// warp tile: 128m x 16n; mainloop split into 2 m-halves with
// inline streaming stores after each half.
// ============================================================
__global__ void __launch_bounds__(THREADS, 2) fft_gemm_kernel(
    const float* __restrict__ x,
    const float* __restrict__ bias,
    float* __restrict__ out)
{
    extern __shared__ char smem[];
    __half* Bs = (__half*)smem;
    // segh[buf][variant][384]; variant1 is shifted by one element
    __half (*segh)[2][384] = (__half(*)[2][384])(smem + SMEM_B_BYTES);

    const int tid  = threadIdx.x;
    const int wid  = tid >> 5;
    const int lane = tid & 31;
    const int q    = lane & 3;
    const int r4   = lane >> 2;
    const int ntile = (int)(blockIdx.x & 3);
    const int e0    = ntile * BN;

    // ---- load B tile (WeffT rows e0..e0+127), permuted within slices ----
    for (int u = tid; u < 4096; u += THREADS) {
        int r  = u >> 5;
        int ch = u & 31;
        int esrc = e0 + (r & ~15) + permcol(r & 15);
        uint4 v = *reinterpret_cast<const uint4*>(&g_weffT[esrc * W_SZ + ch * 8]);
        *reinterpret_cast<uint4*>(Bs + r * PB + ch * 8) = v;
    }

    // ---- per-thread bias: 4 contiguous cols ----
    const int colb = e0 + wid * 16 + 4 * q;
    const float4 bias4 = *reinterpret_cast<const float4*>(bias + colb);

    // ---- ldmatrix base address for this warp's 16-row B slice ----
    const uint32_t sbB = smem_to_u32(Bs);
    const int brow = wid * 16 + (lane & 7) + ((lane & 16) ? 8 : 0);
    const int bkof = (lane & 8) ? 8 : 0;
    const uint32_t baddr0 = sbB + (uint32_t)(brow * PB + bkof) * 2u;

    // ---- per-thread A base: pick alignment variant by parity ----
    const int base0 = r4 + 2 * q;              // 0..13
    const int par   = base0 & 1;
    // byte offset within variant array: (base0 - par + 8i) * 2
    const uint32_t segv_sm[2] = {
        smem_to_u32(&segh[0][par][0]) + (uint32_t)(base0 - par) * 2u,
        smem_to_u32(&segh[1][par][0]) + (uint32_t)(base0 - par) * 2u
    };

    // ---- segment writer helper (writes both alignment variants) ----
    auto seg_store = [&](int buf, int j, float v) {
        __half h = __float2half_rn(v);
        segh[buf][0][j] = h;
        if (j > 0) segh[buf][1][j - 1] = h;
    };

    // ---- initial segment load for first M-tile ----
    const int mt0 = (int)(blockIdx.x >> 2);
    {
        int bidx = mt0 >> 6, t0 = (mt0 & 63) * BM;
        int gx0 = t0 + tid - (W_SZ - 1);
        seg_store(0, tid, (gx0 >= 0) ? x[bidx * T_SZ + gx0] : 0.0f);
        if (tid < 128) {
            int j = 256 + tid;
            int gx1 = t0 + j - (W_SZ - 1);
            seg_store(0, j, (j < 383 && gx1 >= 0) ? x[bidx * T_SZ + gx1] : 0.0f);
        }
    }
    __syncthreads();

    int pb = 0;
    for (int mt = mt0; mt < MTILES; mt += CTAS_PER_N, pb ^= 1) {
        // ---- prefetch next segment into registers (LDG) ----
        const int mtn = mt + CTAS_PER_N;
        float p0 = 0.0f, p1 = 0.0f;
        if (mtn < MTILES) {
            int bidx = mtn >> 6, t0 = (mtn & 63) * BM;
            int gx0 = t0 + tid - (W_SZ - 1);
            if (gx0 >= 0) p0 = x[bidx * T_SZ + gx0];
            if (tid < 128) {
                int j = 256 + tid;
                int gx1 = t0 + j - (W_SZ - 1);
                if (j < 383 && gx1 >= 0) p1 = x[bidx * T_SZ + gx1];
            }
        }

        // ---- preload ALL 47 Toeplitz A-values (1 LDS.32 each) ----
        const uint32_t sga = segv_sm[pb];
        uint32_t av[47];
        #pragma unroll
        for (int i = 0; i < 47; i++) av[i] = lds32(sga + (uint32_t)(16 * i));

        const size_t rowb = (size_t)mt * BM + (size_t)r4;

        // ---- two half-passes: m-tiles [0..3] then [4..7]; stores inline ----
        #pragma unroll
        for (int half = 0; half < 2; half++) {
            float acc[4][2][4];
            #pragma unroll
            for (int m = 0; m < 4; m++)
                #pragma unroll
                for (int n = 0; n < 2; n++)
                    #pragma unroll
                    for (int c = 0; c < 4; c++) acc[m][n][c] = 0.0f;

            #pragma unroll
            for (int ks = 0; ks < 16; ks++) {
                uint32_t b0, b1, b2, b3;
                ldmatrix_x4(b0, b1, b2, b3, baddr0 + (uint32_t)(ks * 32));
                #pragma unroll
                for (int m = 0; m < 4; m++) {
                    const int i0 = 2 * ks + 2 * (half * 4 + m);
                    mma16816(acc[m][0], av[i0], av[i0 + 1], av[i0 + 1], av[i0 + 2],
                             b0, b1);
                    mma16816(acc[m][1], av[i0], av[i0 + 1], av[i0 + 1], av[i0 + 2],
                             b2, b3);
                }
            }

            // inline streaming stores for this half's 4 m-tiles
            #pragma unroll
            for (int m = 0; m < 4; m++) {
                float* o0 = out + (rowb + 16 * (half * 4 + m)) * EMB + colb;
                float* o1 = o0 + 8 * EMB;
                float4 v0 = make_float4(acc[m][0][0] + bias4.x, acc[m][0][1] + bias4.y,
                                        acc[m][1][0] + bias4.z, acc[m][1][1] + bias4.w);
                float4 v1 = make_float4(acc[m][0][2] + bias4.x, acc[m][0][3] + bias4.y,
                                        acc[m][1][2] + bias4.z, acc[m][1][3] + bias4.w);
                stcs128(o0, v0);
                stcs128(o1, v1);
            }
        }

        // ---- store prefetched segment into alternate buffer ----
        if (mtn < MTILES) {
            seg_store(pb ^ 1, tid, p0);
            if (tid < 128) seg_store(pb ^ 1, 256 + tid, p1);
        }
        __syncthreads();   // next seg visible; old seg free
    }
}

// ============================================================
extern "C" void kernel_launch(void* const* d_in, const int* in_sizes, int n_in,
                              void* d_out, int out_size) {
    const float* x  = nullptr;
    const float* wt = nullptr;
    const float* bs = nullptr;
    for (int i = 0; i < n_in; i++) {
        if (in_sizes[i] == B_SZ * T_SZ)        x  = (const float*)d_in[i];
        else if (in_sizes[i] == EMB * NFEAT)   wt = (const float*)d_in[i];
        else if (in_sizes[i] == EMB)           bs = (const float*)d_in[i];
    }

    weff_kernel<<<EMB, 256>>>(wt);

    cudaFuncSetAttribute(fft_gemm_kernel,
                         cudaFuncAttributeMaxDynamicSharedMemorySize, SMEM_TOTAL);
    fft_gemm_kernel<<<GRID, THREADS, SMEM_TOTAL>>>(x, bs, (float*)d_out);
}